// round 10
// baseline (speedup 1.0000x reference)
#include <cuda_runtime.h>
#include <cuda_bf16.h>
#include <cstdint>

// ---------------------------------------------------------------------------
// Problem constants
// ---------------------------------------------------------------------------
#define LQ      22223
#define CDIM    256
#define NHEADS  8
#define NLVL    4
#define NPTS    4
#define KDIM    256

__device__ __constant__ int c_H[NLVL]     = {100, 50, 25, 13};
__device__ __constant__ int c_W[NLVL]     = {167, 84, 42, 21};
__device__ __constant__ int c_start[NLVL] = {0, 16700, 20900, 21950};

// ---------------------------------------------------------------------------
// Scratch (device globals; no allocation allowed)
// ---------------------------------------------------------------------------
__device__ float g_v   [LQ * CDIM];   // value @ W_val + b_val
__device__ float g_oa  [LQ * 384];    // [off(256) | attn logits(128)] per row
__device__ float g_mid [LQ * CDIM];   // sampled output, pre-W_out

// Weight splits, transposed to [N,K], packed: WVAL | WOFF | WATTN | WOUT
#define W_VAL_OFF   0
#define W_OFF_OFF   (256 * 256)
#define W_ATTN_OFF  (2 * 256 * 256)
#define W_OUT_OFF   (2 * 256 * 256 + 128 * 256)
#define W_TOTAL     (3 * 256 * 256 + 128 * 256)
__device__ __nv_bfloat16 g_wh[W_TOTAL];
__device__ __nv_bfloat16 g_wl[W_TOTAL];

// ---------------------------------------------------------------------------
// mma.sync / ldmatrix helpers (plain sm_103)
// ---------------------------------------------------------------------------
__device__ __forceinline__ uint32_t smem_u32(const void* p) {
    uint32_t a;
    asm("{ .reg .u64 t; cvta.to.shared.u64 t, %1; cvt.u32.u64 %0, t; }"
        : "=r"(a) : "l"(p));
    return a;
}
__device__ __forceinline__ void ldsm_x4(uint32_t* r, uint32_t addr) {
    asm volatile("ldmatrix.sync.aligned.m8n8.x4.shared.b16 {%0,%1,%2,%3}, [%4];"
                 : "=r"(r[0]), "=r"(r[1]), "=r"(r[2]), "=r"(r[3]) : "r"(addr));
}
__device__ __forceinline__ void mma_bf16(float* d, const uint32_t* a,
                                         const uint32_t* b) {
    asm volatile(
        "mma.sync.aligned.m16n8k16.row.col.f32.bf16.bf16.f32 "
        "{%0,%1,%2,%3}, {%4,%5,%6,%7}, {%8,%9}, {%0,%1,%2,%3};"
        : "+f"(d[0]), "+f"(d[1]), "+f"(d[2]), "+f"(d[3])
        : "r"(a[0]), "r"(a[1]), "r"(a[2]), "r"(a[3]), "r"(b[0]), "r"(b[1]));
}

// ---------------------------------------------------------------------------
// Fused weight prep
// ---------------------------------------------------------------------------
__global__ void prep_all_w(const float* __restrict__ Wv,
                           const float* __restrict__ Wo,
                           const float* __restrict__ Wa,
                           const float* __restrict__ Wu,
                           __nv_bfloat16* __restrict__ wh,
                           __nv_bfloat16* __restrict__ wl)
{
    int i = blockIdx.x * blockDim.x + threadIdx.x;
    if (i >= W_TOTAL) return;
    const float* W;
    int N, local, base;
    if (i < 65536)        { W = Wv; N = 256; base = W_VAL_OFF;  local = i; }
    else if (i < 131072)  { W = Wo; N = 256; base = W_OFF_OFF;  local = i - 65536; }
    else if (i < 163840)  { W = Wa; N = 128; base = W_ATTN_OFF; local = i - 131072; }
    else                  { W = Wu; N = 256; base = W_OUT_OFF;  local = i - 163840; }
    int k = local / N;
    int n = local - k * N;
    float a = W[(size_t)k * N + n];
    __nv_bfloat16 hi = __float2bfloat16(a);
    __nv_bfloat16 lo = __float2bfloat16(a - __bfloat162float(hi));
    wh[(size_t)base + (size_t)n * KDIM + k] = hi;
    wl[(size_t)base + (size_t)n * KDIM + k] = lo;
}

// ---------------------------------------------------------------------------
// Split-bf16 mma.sync GEMM core, K processed in TWO chunks of 128 so SMEM
// drops to ~102KB/CTA -> 2 CTAs per SM (16 warps). 256 thr, warp tile 32x32.
// ---------------------------------------------------------------------------
#define LDK2  136                        // bf16 elems per SMEM row (128 + 8 pad)
#define SMA_H 0
#define SMA_L (128 * LDK2 * 2)           // 34816
#define SMB_H (2 * 128 * LDK2 * 2)       // 69632
#define SMB_L (SMB_H + 64 * LDK2 * 2)    // 87040
#define SM_TOTAL (SMB_L + 64 * LDK2 * 2) // 104448

__device__ __forceinline__ void gemm_core(
    const float* __restrict__ A,
    const __nv_bfloat16* __restrict__ bh,   // B hi base for this col-tile [64,K]
    const __nv_bfloat16* __restrict__ bl,
    const float* __restrict__ bias0,
    const float* __restrict__ bias1,
    int nsplit, int col0,
    float* __restrict__ C, int M, int N, int m0, char* smem)
{
    __nv_bfloat16* Ah = reinterpret_cast<__nv_bfloat16*>(smem + SMA_H);
    __nv_bfloat16* Al = reinterpret_cast<__nv_bfloat16*>(smem + SMA_L);
    __nv_bfloat16* Bh = reinterpret_cast<__nv_bfloat16*>(smem + SMB_H);
    __nv_bfloat16* Bl = reinterpret_cast<__nv_bfloat16*>(smem + SMB_L);

    const int tid  = threadIdx.x;
    const int wid  = tid >> 5;
    const int lane = tid & 31;
    const int warp_m = wid & 3;
    const int warp_n = wid >> 2;

    float acc[2][4][4];
    #pragma unroll
    for (int i = 0; i < 2; i++)
        #pragma unroll
        for (int j = 0; j < 4; j++)
            #pragma unroll
            for (int k = 0; k < 4; k++) acc[i][j][k] = 0.0f;

    const uint32_t sAh = smem_u32(Ah), sAl = smem_u32(Al);
    const uint32_t sBh = smem_u32(Bh), sBl = smem_u32(Bl);
    const int a_row  = warp_m * 32 + (lane & 15);
    const int a_colb = (lane >> 4) << 3;
    const int b_row  = warp_n * 32 + (lane & 7) + ((lane >> 4) << 3);
    const int b_colb = ((lane >> 3) & 1) << 3;

    #pragma unroll 1
    for (int chunk = 0; chunk < 2; ++chunk) {
        const int k0 = chunk << 7;

        // ---- load A chunk (fp32) and split to hi/lo bf16 in SMEM ----
        {
            const int r  = tid >> 1;              // 0..127
            const int cb = (tid & 1) * 64;        // half-chunk base
            const int gr = m0 + r;
            #pragma unroll
            for (int j = 0; j < 16; j++) {
                const int c4 = cb + j * 4;
                float4 v = make_float4(0.f, 0.f, 0.f, 0.f);
                if (gr < M)
                    v = *reinterpret_cast<const float4*>(
                        &A[(size_t)gr * KDIM + k0 + c4]);
                __nv_bfloat162 h01 = __floats2bfloat162_rn(v.x, v.y);
                __nv_bfloat162 h23 = __floats2bfloat162_rn(v.z, v.w);
                __nv_bfloat162 l01 = __floats2bfloat162_rn(
                    v.x - __bfloat162float(h01.x), v.y - __bfloat162float(h01.y));
                __nv_bfloat162 l23 = __floats2bfloat162_rn(
                    v.z - __bfloat162float(h23.x), v.w - __bfloat162float(h23.y));
                const int o = r * LDK2 + c4;
                uint2 hu, lu;
                hu.x = *reinterpret_cast<uint32_t*>(&h01);
                hu.y = *reinterpret_cast<uint32_t*>(&h23);
                lu.x = *reinterpret_cast<uint32_t*>(&l01);
                lu.y = *reinterpret_cast<uint32_t*>(&l23);
                *reinterpret_cast<uint2*>(&Ah[o]) = hu;
                *reinterpret_cast<uint2*>(&Al[o]) = lu;
            }
        }
        // ---- load B chunk hi/lo ([64, 128] slice) ----
        #pragma unroll
        for (int i = 0; i < 4; i++) {
            const int idx = tid + (i << 8);
            const int r  = idx >> 4;              // 0..63
            const int c8 = (idx & 15) << 3;       // 0..120
            const size_t g = (size_t)r * KDIM + k0 + c8;
            const int o = r * LDK2 + c8;
            *reinterpret_cast<uint4*>(&Bh[o]) =
                *reinterpret_cast<const uint4*>(&bh[g]);
            *reinterpret_cast<uint4*>(&Bl[o]) =
                *reinterpret_cast<const uint4*>(&bl[g]);
        }
        __syncthreads();

        // ---- MMA: 8 K-steps x 3 split-products ----
        #pragma unroll
        for (int ks = 0; ks < 8; ks++) {
            const int kc = ks << 4;
            uint32_t fah[2][4], fal[2][4], fbh[2][4], fbl[2][4];
            #pragma unroll
            for (int mt = 0; mt < 2; mt++) {
                const uint32_t off =
                    (uint32_t)(((a_row + mt * 16) * LDK2 + kc + a_colb) * 2);
                ldsm_x4(fah[mt], sAh + off);
                ldsm_x4(fal[mt], sAl + off);
            }
            #pragma unroll
            for (int np = 0; np < 2; np++) {
                const uint32_t off =
                    (uint32_t)(((b_row + np * 16) * LDK2 + kc + b_colb) * 2);
                ldsm_x4(fbh[np], sBh + off);
                ldsm_x4(fbl[np], sBl + off);
            }
            #pragma unroll
            for (int mt = 0; mt < 2; mt++)
                #pragma unroll
                for (int nt = 0; nt < 4; nt++)
                    mma_bf16(acc[mt][nt], fah[mt], &fbh[nt >> 1][(nt & 1) * 2]);
            #pragma unroll
            for (int mt = 0; mt < 2; mt++)
                #pragma unroll
                for (int nt = 0; nt < 4; nt++)
                    mma_bf16(acc[mt][nt], fah[mt], &fbl[nt >> 1][(nt & 1) * 2]);
            #pragma unroll
            for (int mt = 0; mt < 2; mt++)
                #pragma unroll
                for (int nt = 0; nt < 4; nt++)
                    mma_bf16(acc[mt][nt], fal[mt], &fbh[nt >> 1][(nt & 1) * 2]);
        }
        __syncthreads();
    }

    // ---- epilogue ----
    const int er = lane >> 2;
    const int ec = (lane & 3) << 1;
    #pragma unroll
    for (int mt = 0; mt < 2; mt++) {
        #pragma unroll
        for (int nt = 0; nt < 4; nt++) {
            const int col = col0 + warp_n * 32 + nt * 8 + ec;
            const float b0 = (col < nsplit)     ? bias0[col]     : bias1[col - nsplit];
            const float b1 = (col + 1 < nsplit) ? bias0[col + 1] : bias1[col + 1 - nsplit];
            const int r0 = m0 + warp_m * 32 + mt * 16 + er;
            if (r0 < M) {
                float2 o = make_float2(acc[mt][nt][0] + b0, acc[mt][nt][1] + b1);
                *reinterpret_cast<float2*>(&C[(size_t)r0 * N + col]) = o;
            }
            if (r0 + 8 < M) {
                float2 o = make_float2(acc[mt][nt][2] + b0, acc[mt][nt][3] + b1);
                *reinterpret_cast<float2*>(&C[(size_t)(r0 + 8) * N + col]) = o;
            }
        }
    }
}

// Merged front GEMM: grid.y 0..3 -> value GEMM (N=256, C=g_v),
//                    grid.y 4..9 -> query GEMM (N=384, C=g_oa, bias split 256)
__global__ __launch_bounds__(256, 2)
void gemm_front(const float* __restrict__ value,
                const float* __restrict__ query,
                const __nv_bfloat16* __restrict__ wh,
                const __nv_bfloat16* __restrict__ wl,
                const float* __restrict__ b_val,
                const float* __restrict__ b_off,
                const float* __restrict__ b_attn,
                float* __restrict__ Cv, float* __restrict__ Coa)
{
    extern __shared__ __align__(16) char smem[];
    const int y = blockIdx.y;
    const int m0 = blockIdx.x * 128;
    if (y < 4) {
        const int col0 = y * 64;
        gemm_core(value, wh + W_VAL_OFF + (size_t)col0 * KDIM,
                  wl + W_VAL_OFF + (size_t)col0 * KDIM,
                  b_val, b_val, 1 << 30, col0, Cv, LQ, 256, m0, smem);
    } else {
        const int col0 = (y - 4) * 64;
        gemm_core(query, wh + W_OFF_OFF + (size_t)col0 * KDIM,
                  wl + W_OFF_OFF + (size_t)col0 * KDIM,
                  b_off, b_attn, 256, col0, Coa, LQ, 384, m0, smem);
    }
}

// Output GEMM
__global__ __launch_bounds__(256, 2)
void gemm_out(const float* __restrict__ mid,
              const __nv_bfloat16* __restrict__ wh,
              const __nv_bfloat16* __restrict__ wl,
              const float* __restrict__ b_out,
              float* __restrict__ C)
{
    extern __shared__ __align__(16) char smem[];
    const int col0 = blockIdx.y * 64;
    gemm_core(mid, wh + W_OUT_OFF + (size_t)col0 * KDIM,
              wl + W_OUT_OFF + (size_t)col0 * KDIM,
              b_out, b_out, 1 << 30, col0, C, LQ, 256, blockIdx.x * 128, smem);
}

// ---------------------------------------------------------------------------
// Sampling: phase 1 per-point metadata (int2-fused), phase 2 gather.
// ---------------------------------------------------------------------------
__global__ __launch_bounds__(256) void sample_kernel(
    const float* __restrict__ v, const float* __restrict__ oa,
    const float* __restrict__ ref, float* __restrict__ mid)
{
    __shared__ int2 s_meta[128 * 4];   // {elem offset (h*32 folded), weight bits}

    const int q   = blockIdx.x;
    const int tid = threadIdx.x;

    // ---- Phase 1 ----
    if (tid < 128) {
        const int h  = tid >> 4;
        const int l  = (tid >> 2) & 3;
        const int p  = tid & 3;

        float lg = oa[(size_t)q * 384 + 256 + h * 16 + l * 4 + p];
        float mx = lg;
        #pragma unroll
        for (int m = 8; m; m >>= 1) mx = fmaxf(mx, __shfl_xor_sync(~0u, mx, m));
        float ex = __expf(lg - mx);
        float sm = ex;
        #pragma unroll
        for (int m = 8; m; m >>= 1) sm += __shfl_xor_sync(~0u, sm, m);
        const float wn = ex / sm;

        const float ox = oa[(size_t)q * 384 + h * 32 + l * 8 + p * 2 + 0];
        const float oy = oa[(size_t)q * 384 + h * 32 + l * 8 + p * 2 + 1];
        const float cx = ref[(size_t)q * 16 + l * 4 + 0];
        const float cy = ref[(size_t)q * 16 + l * 4 + 1];
        const float rw = ref[(size_t)q * 16 + l * 4 + 2];
        const float rh = ref[(size_t)q * 16 + l * 4 + 3];
        const int H = c_H[l], W = c_W[l];
        const int start = c_start[l];

        const float x = (cx + ox * 0.125f * rw) * (float)W - 0.5f;
        const float y = (cy + oy * 0.125f * rh) * (float)H - 0.5f;
        const float x0f = floorf(x), y0f = floorf(y);
        const int x0 = (int)x0f, y0 = (int)y0f;
        const float wx1 = x - x0f, wy1 = y - y0f;
        const float wx0 = 1.0f - wx1, wy0 = 1.0f - wy1;

        const bool vx0 = (x0 >= 0) && (x0 < W);
        const bool vx1 = (x0 + 1 >= 0) && (x0 + 1 < W);
        const bool vy0 = (y0 >= 0) && (y0 < H);
        const bool vy1 = (y0 + 1 >= 0) && (y0 + 1 < H);

        const int xc0 = min(max(x0, 0), W - 1);
        const int xc1 = min(max(x0 + 1, 0), W - 1);
        const int yc0 = min(max(y0, 0), H - 1);
        const int yc1 = min(max(y0 + 1, 0), H - 1);

        const int hb = h * 32;
        const int r0 = (start + yc0 * W) * CDIM + hb;
        const int r1 = (start + yc1 * W) * CDIM + hb;
        const int b = tid * 4;
        s_meta[b + 0] = make_int2(r0 + xc0 * CDIM,
            __float_as_int((vy0 && vx0) ? wn * wy0 * wx0 : 0.0f));
        s_meta[b + 1] = make_int2(r0 + xc1 * CDIM,
            __float_as_int((vy0 && vx1) ? wn * wy0 * wx1 : 0.0f));
        s_meta[b + 2] = make_int2(r1 + xc0 * CDIM,
            __float_as_int((vy1 && vx0) ? wn * wy1 * wx0 : 0.0f));
        s_meta[b + 3] = make_int2(r1 + xc1 * CDIM,
            __float_as_int((vy1 && vx1) ? wn * wy1 * wx1 : 0.0f));
    }
    __syncthreads();

    // ---- Phase 2: gather ----
    const int h    = tid >> 5;
    const int lane = tid & 31;
    const int cg   = lane >> 3;
    const int sc   = (lane & 7) * 4;
    const float* vp = v + sc;          // hoisted channel offset

    float4 acc = make_float4(0.f, 0.f, 0.f, 0.f);
    const int2* mp = &s_meta[h * 64 + cg];

    #pragma unroll
    for (int pt = 0; pt < 16; pt++) {
        const int2  m = mp[pt * 4];
        const float w = __int_as_float(m.y);
        const float4 vv = *reinterpret_cast<const float4*>(vp + m.x);
        acc.x = fmaf(w, vv.x, acc.x);
        acc.y = fmaf(w, vv.y, acc.y);
        acc.z = fmaf(w, vv.z, acc.z);
        acc.w = fmaf(w, vv.w, acc.w);
    }

    #pragma unroll
    for (int m = 8; m <= 16; m <<= 1) {
        acc.x += __shfl_xor_sync(~0u, acc.x, m);
        acc.y += __shfl_xor_sync(~0u, acc.y, m);
        acc.z += __shfl_xor_sync(~0u, acc.z, m);
        acc.w += __shfl_xor_sync(~0u, acc.w, m);
    }
    if (lane < 8)
        *reinterpret_cast<float4*>(&mid[(size_t)q * CDIM + h * 32 + sc]) = acc;
}

// ---------------------------------------------------------------------------
// Launch
// ---------------------------------------------------------------------------
extern "C" void kernel_launch(void* const* d_in, const int* in_sizes, int n_in,
                              void* d_out, int out_size)
{
    const float* query  = (const float*)d_in[0];
    const float* ref    = (const float*)d_in[1];
    const float* value  = (const float*)d_in[2];
    const float* W_off  = (const float*)d_in[3];
    const float* b_off  = (const float*)d_in[4];
    const float* W_attn = (const float*)d_in[5];
    const float* b_attn = (const float*)d_in[6];
    const float* W_val  = (const float*)d_in[7];
    const float* b_val  = (const float*)d_in[8];
    const float* W_out  = (const float*)d_in[9];
    const float* b_out  = (const float*)d_in[10];
    float* out = (float*)d_out;

    float *gv, *goa, *gmid;
    __nv_bfloat16 *wh, *wl;
    cudaGetSymbolAddress((void**)&gv,   g_v);
    cudaGetSymbolAddress((void**)&goa,  g_oa);
    cudaGetSymbolAddress((void**)&gmid, g_mid);
    cudaGetSymbolAddress((void**)&wh,   g_wh);
    cudaGetSymbolAddress((void**)&wl,   g_wl);

    cudaFuncSetAttribute(gemm_front, cudaFuncAttributeMaxDynamicSharedMemorySize,
                         SM_TOTAL);
    cudaFuncSetAttribute(gemm_out, cudaFuncAttributeMaxDynamicSharedMemorySize,
                         SM_TOTAL);

    const int MT = (LQ + 127) / 128;   // 174

    // 0. weight prep
    prep_all_w<<<(W_TOTAL + 255) / 256, 256>>>(W_val, W_off, W_attn, W_out, wh, wl);

    // 1. merged front GEMMs
    gemm_front<<<dim3(MT, 10), 256, SM_TOTAL>>>(value, query, wh, wl,
                                                b_val, b_off, b_attn, gv, goa);
    // 2. sampling (softmax fused, two-phase)
    sample_kernel<<<LQ, 256>>>(gv, goa, ref, gmid);
    // 3. out = mid @ W_out + b_out
    gemm_out<<<dim3(MT, 4), 256, SM_TOTAL>>>(gmid, wh, wl, b_out, out);
}

// round 12
// speedup vs baseline: 1.2382x; 1.2382x over previous
#include <cuda_runtime.h>
#include <cuda_bf16.h>
#include <cstdint>

// ---------------------------------------------------------------------------
// Problem constants
// ---------------------------------------------------------------------------
#define LQ      22223
#define LQP     22272                 // padded to 174*128
#define CDIM    256
#define NHEADS  8
#define NLVL    4
#define NPTS    4
#define KDIM    256

__device__ __constant__ int c_H[NLVL]     = {100, 50, 25, 13};
__device__ __constant__ int c_W[NLVL]     = {167, 84, 42, 21};
__device__ __constant__ int c_start[NLVL] = {0, 16700, 20900, 21950};

// ---------------------------------------------------------------------------
// Scratch (device globals; zero-initialized at module load — pad rows stay 0)
// ---------------------------------------------------------------------------
__device__ float g_v   [LQP * CDIM];  // value @ W_val + b_val (fp32, for gather)
__device__ float g_oa  [LQP * 384];   // [off(256) | attn logits(128)] per row

__device__ __nv_bfloat16 g_avh[LQP * CDIM];  // value split hi
__device__ __nv_bfloat16 g_avl[LQP * CDIM];  // value split lo
__device__ __nv_bfloat16 g_aqh[LQP * CDIM];  // query split hi
__device__ __nv_bfloat16 g_aql[LQP * CDIM];  // query split lo
__device__ __nv_bfloat16 g_amh[LQP * CDIM];  // mid   split hi (from sampler)
__device__ __nv_bfloat16 g_aml[LQP * CDIM];  // mid   split lo

// Weight splits, transposed to [N,K], packed: WVAL | WOFF | WATTN | WOUT
#define W_VAL_OFF   0
#define W_OFF_OFF   (256 * 256)
#define W_ATTN_OFF  (2 * 256 * 256)
#define W_OUT_OFF   (2 * 256 * 256 + 128 * 256)
#define W_TOTAL     (3 * 256 * 256 + 128 * 256)
__device__ __nv_bfloat16 g_wh[W_TOTAL];
__device__ __nv_bfloat16 g_wl[W_TOTAL];

// ---------------------------------------------------------------------------
// mma.sync / ldmatrix / cp.async helpers (plain sm_103)
// ---------------------------------------------------------------------------
__device__ __forceinline__ uint32_t smem_u32(const void* p) {
    uint32_t a;
    asm("{ .reg .u64 t; cvta.to.shared.u64 t, %1; cvt.u32.u64 %0, t; }"
        : "=r"(a) : "l"(p));
    return a;
}
__device__ __forceinline__ void ldsm_x4(uint32_t* r, uint32_t addr) {
    asm volatile("ldmatrix.sync.aligned.m8n8.x4.shared.b16 {%0,%1,%2,%3}, [%4];"
                 : "=r"(r[0]), "=r"(r[1]), "=r"(r[2]), "=r"(r[3]) : "r"(addr));
}
__device__ __forceinline__ void mma_bf16(float* d, const uint32_t* a,
                                         const uint32_t* b) {
    asm volatile(
        "mma.sync.aligned.m16n8k16.row.col.f32.bf16.bf16.f32 "
        "{%0,%1,%2,%3}, {%4,%5,%6,%7}, {%8,%9}, {%0,%1,%2,%3};"
        : "+f"(d[0]), "+f"(d[1]), "+f"(d[2]), "+f"(d[3])
        : "r"(a[0]), "r"(a[1]), "r"(a[2]), "r"(a[3]), "r"(b[0]), "r"(b[1]));
}
__device__ __forceinline__ void cp16(uint32_t dst, const void* src) {
    asm volatile("cp.async.cg.shared.global [%0], [%1], 16;"
                 :: "r"(dst), "l"(src) : "memory");
}
#define CP_COMMIT() asm volatile("cp.async.commit_group;" ::: "memory")
#define CP_WAIT0()  asm volatile("cp.async.wait_group 0;" ::: "memory")

// ---------------------------------------------------------------------------
// Prep: split all four fp32 W[K,N] into bf16 hi/lo at [N,K].
// ---------------------------------------------------------------------------
__global__ void prep_all_w(const float* __restrict__ Wv,
                           const float* __restrict__ Wo,
                           const float* __restrict__ Wa,
                           const float* __restrict__ Wu,
                           __nv_bfloat16* __restrict__ wh,
                           __nv_bfloat16* __restrict__ wl)
{
    int i = blockIdx.x * blockDim.x + threadIdx.x;
    if (i >= W_TOTAL) return;
    const float* W;
    int N, local, base;
    if (i < 65536)        { W = Wv; N = 256; base = W_VAL_OFF;  local = i; }
    else if (i < 131072)  { W = Wo; N = 256; base = W_OFF_OFF;  local = i - 65536; }
    else if (i < 163840)  { W = Wa; N = 128; base = W_ATTN_OFF; local = i - 131072; }
    else                  { W = Wu; N = 256; base = W_OUT_OFF;  local = i - 163840; }
    int k = local / N;
    int n = local - k * N;
    float a = W[(size_t)k * N + n];
    __nv_bfloat16 hi = __float2bfloat16(a);
    __nv_bfloat16 lo = __float2bfloat16(a - __bfloat162float(hi));
    wh[(size_t)base + (size_t)n * KDIM + k] = hi;
    wl[(size_t)base + (size_t)n * KDIM + k] = lo;
}

// Split value+query (fp32 [LQ,256]) into bf16 hi/lo. One float4 per thread-idx.
__global__ void split_av(const float* __restrict__ value,
                         const float* __restrict__ query,
                         __nv_bfloat16* __restrict__ avh,
                         __nv_bfloat16* __restrict__ avl,
                         __nv_bfloat16* __restrict__ aqh,
                         __nv_bfloat16* __restrict__ aql)
{
    const int n4 = LQ * 64;            // float4 count per tensor
    int i = blockIdx.x * blockDim.x + threadIdx.x;
    if (i >= 2 * n4) return;
    const float* src;
    __nv_bfloat16 *dh, *dl;
    int j;
    if (i < n4) { src = value; dh = g_avh; dl = g_avl; j = i; }
    else        { src = query; dh = g_aqh; dl = g_aql; j = i - n4; }
    (void)avh; (void)avl; (void)aqh; (void)aql;
    float4 v = *reinterpret_cast<const float4*>(src + (size_t)j * 4);
    __nv_bfloat162 h01 = __floats2bfloat162_rn(v.x, v.y);
    __nv_bfloat162 h23 = __floats2bfloat162_rn(v.z, v.w);
    __nv_bfloat162 l01 = __floats2bfloat162_rn(
        v.x - __bfloat162float(h01.x), v.y - __bfloat162float(h01.y));
    __nv_bfloat162 l23 = __floats2bfloat162_rn(
        v.z - __bfloat162float(h23.x), v.w - __bfloat162float(h23.y));
    uint2 hu, lu;
    hu.x = *reinterpret_cast<uint32_t*>(&h01);
    hu.y = *reinterpret_cast<uint32_t*>(&h23);
    lu.x = *reinterpret_cast<uint32_t*>(&l01);
    lu.y = *reinterpret_cast<uint32_t*>(&l23);
    *reinterpret_cast<uint2*>(dh + (size_t)j * 4) = hu;
    *reinterpret_cast<uint2*>(dl + (size_t)j * 4) = lu;
}

// ---------------------------------------------------------------------------
// Split-bf16 mma.sync GEMM core. A pre-split bf16 hi/lo. K=256 resident.
// Prologue is pure cp.async. 256 thr, 8 warps, warp tile 32x32, 1 CTA/SM.
// ---------------------------------------------------------------------------
#define LDK 264
#define SM_AH 0
#define SM_AL (128 * LDK * 2)            //  67584
#define SM_BH (2 * 128 * LDK * 2)        // 135168
#define SM_BL (SM_BH + 64 * LDK * 2)     // 168960
#define SM_TOTAL (SM_BL + 64 * LDK * 2)  // 202752

__device__ __forceinline__ void gemm_core(
    const __nv_bfloat16* __restrict__ ah,   // A hi [LQP, 256]
    const __nv_bfloat16* __restrict__ al,
    const __nv_bfloat16* __restrict__ bh,   // B hi base for this col-tile [64,K]
    const __nv_bfloat16* __restrict__ bl,
    const float* __restrict__ bias0,
    const float* __restrict__ bias1,
    int nsplit, int col0,
    float* __restrict__ C, int M, int N, int m0, char* smem)
{
    const int tid  = threadIdx.x;
    const int wid  = tid >> 5;
    const int lane = tid & 31;
    const int warp_m = wid & 3;
    const int warp_n = wid >> 2;

    const uint32_t sAh = smem_u32(smem + SM_AH);
    const uint32_t sAl = smem_u32(smem + SM_AL);
    const uint32_t sBh = smem_u32(smem + SM_BH);
    const uint32_t sBl = smem_u32(smem + SM_BL);

    // ---- prologue: pure async copies (no converts, no guards: A padded) ----
    #pragma unroll
    for (int i = 0; i < 16; i++) {
        const int idx = tid + (i << 8);
        const int r  = idx >> 5;             // 0..127
        const int ce = (idx & 31) << 3;      // elem 0..248
        const uint32_t so = (uint32_t)((r * LDK + ce) * 2);
        const size_t g = (size_t)(m0 + r) * CDIM + ce;
        cp16(sAh + so, ah + g);
        cp16(sAl + so, al + g);
    }
    #pragma unroll
    for (int i = 0; i < 8; i++) {
        const int idx = tid + (i << 8);
        const int r  = idx >> 5;             // 0..63
        const int ce = (idx & 31) << 3;
        const uint32_t so = (uint32_t)((r * LDK + ce) * 2);
        const size_t g = (size_t)r * KDIM + ce;
        cp16(sBh + so, bh + g);
        cp16(sBl + so, bl + g);
    }
    CP_COMMIT();
    CP_WAIT0();
    __syncthreads();

    // ---- mainloop: 16 K-steps x 3 split-products, no barriers ----
    float acc[2][4][4];
    #pragma unroll
    for (int i = 0; i < 2; i++)
        #pragma unroll
        for (int j = 0; j < 4; j++)
            #pragma unroll
            for (int k = 0; k < 4; k++) acc[i][j][k] = 0.0f;

    const int a_row  = warp_m * 32 + (lane & 15);
    const int a_colb = (lane >> 4) << 3;
    const int b_row  = warp_n * 32 + (lane & 7) + ((lane >> 4) << 3);
    const int b_colb = ((lane >> 3) & 1) << 3;

    #pragma unroll
    for (int ks = 0; ks < 16; ks++) {
        const int kc = ks << 4;
        uint32_t fah[2][4], fal[2][4], fbh[2][4], fbl[2][4];
        #pragma unroll
        for (int mt = 0; mt < 2; mt++) {
            const uint32_t off = (uint32_t)(((a_row + mt * 16) * LDK + kc + a_colb) * 2);
            ldsm_x4(fah[mt], sAh + off);
            ldsm_x4(fal[mt], sAl + off);
        }
        #pragma unroll
        for (int np = 0; np < 2; np++) {
            const uint32_t off = (uint32_t)(((b_row + np * 16) * LDK + kc + b_colb) * 2);
            ldsm_x4(fbh[np], sBh + off);
            ldsm_x4(fbl[np], sBl + off);
        }
        #pragma unroll
        for (int mt = 0; mt < 2; mt++)
            #pragma unroll
            for (int nt = 0; nt < 4; nt++)
                mma_bf16(acc[mt][nt], fah[mt], &fbh[nt >> 1][(nt & 1) * 2]);
        #pragma unroll
        for (int mt = 0; mt < 2; mt++)
            #pragma unroll
            for (int nt = 0; nt < 4; nt++)
                mma_bf16(acc[mt][nt], fah[mt], &fbl[nt >> 1][(nt & 1) * 2]);
        #pragma unroll
        for (int mt = 0; mt < 2; mt++)
            #pragma unroll
            for (int nt = 0; nt < 4; nt++)
                mma_bf16(acc[mt][nt], fal[mt], &fbh[nt >> 1][(nt & 1) * 2]);
    }

    // ---- epilogue ----
    const int er = lane >> 2;
    const int ec = (lane & 3) << 1;
    #pragma unroll
    for (int mt = 0; mt < 2; mt++) {
        #pragma unroll
        for (int nt = 0; nt < 4; nt++) {
            const int col = col0 + warp_n * 32 + nt * 8 + ec;
            const float b0 = (col < nsplit)     ? bias0[col]     : bias1[col - nsplit];
            const float b1 = (col + 1 < nsplit) ? bias0[col + 1] : bias1[col + 1 - nsplit];
            const int r0 = m0 + warp_m * 32 + mt * 16 + er;
            if (r0 < M) {
                float2 o = make_float2(acc[mt][nt][0] + b0, acc[mt][nt][1] + b1);
                *reinterpret_cast<float2*>(&C[(size_t)r0 * N + col]) = o;
            }
            if (r0 + 8 < M) {
                float2 o = make_float2(acc[mt][nt][2] + b0, acc[mt][nt][3] + b1);
                *reinterpret_cast<float2*>(&C[(size_t)(r0 + 8) * N + col]) = o;
            }
        }
    }
}

// Merged front GEMM: grid.y 0..3 -> value GEMM (N=256, C=g_v),
//                    grid.y 4..9 -> query GEMM (N=384, C=g_oa, bias split 256)
__global__ __launch_bounds__(256)
void gemm_front(const __nv_bfloat16* __restrict__ wh,
                const __nv_bfloat16* __restrict__ wl,
                const float* __restrict__ b_val,
                const float* __restrict__ b_off,
                const float* __restrict__ b_attn,
                float* __restrict__ Cv, float* __restrict__ Coa)
{
    extern __shared__ __align__(16) char smem[];
    const int y = blockIdx.y;
    const int m0 = blockIdx.x * 128;
    if (y < 4) {
        const int col0 = y * 64;
        gemm_core(g_avh, g_avl,
                  wh + W_VAL_OFF + (size_t)col0 * KDIM,
                  wl + W_VAL_OFF + (size_t)col0 * KDIM,
                  b_val, b_val, 1 << 30, col0, Cv, LQP, 256, m0, smem);
    } else {
        const int col0 = (y - 4) * 64;
        gemm_core(g_aqh, g_aql,
                  wh + W_OFF_OFF + (size_t)col0 * KDIM,
                  wl + W_OFF_OFF + (size_t)col0 * KDIM,
                  b_off, b_attn, 256, col0, Coa, LQP, 384, m0, smem);
    }
}

// Output GEMM (A = mid hi/lo produced by sampler)
__global__ __launch_bounds__(256)
void gemm_out(const __nv_bfloat16* __restrict__ wh,
              const __nv_bfloat16* __restrict__ wl,
              const float* __restrict__ b_out,
              float* __restrict__ C)
{
    extern __shared__ __align__(16) char smem[];
    const int col0 = blockIdx.y * 64;
    gemm_core(g_amh, g_aml,
              wh + W_OUT_OFF + (size_t)col0 * KDIM,
              wl + W_OUT_OFF + (size_t)col0 * KDIM,
              b_out, b_out, 1 << 30, col0, C, LQ, 256, blockIdx.x * 128, smem);
}

// ---------------------------------------------------------------------------
// Sampling: phase 1 per-point metadata, phase 2 gather. Emits mid as bf16
// hi/lo directly (feeds gemm_out without a split pass).
// ---------------------------------------------------------------------------
__global__ __launch_bounds__(256) void sample_kernel(
    const float* __restrict__ v, const float* __restrict__ oa,
    const float* __restrict__ ref)
{
    __shared__ int2 s_meta[128 * 4];   // {elem offset (h*32 folded), weight bits}

    const int q   = blockIdx.x;
    const int tid = threadIdx.x;

    // ---- Phase 1 ----
    if (tid < 128) {
        const int h  = tid >> 4;
        const int l  = (tid >> 2) & 3;
        const int p  = tid & 3;

        float lg = oa[(size_t)q * 384 + 256 + h * 16 + l * 4 + p];
        float mx = lg;
        #pragma unroll
        for (int m = 8; m; m >>= 1) mx = fmaxf(mx, __shfl_xor_sync(~0u, mx, m));
        float ex = __expf(lg - mx);
        float sm = ex;
        #pragma unroll
        for (int m = 8; m; m >>= 1) sm += __shfl_xor_sync(~0u, sm, m);
        const float wn = ex / sm;

        const float ox = oa[(size_t)q * 384 + h * 32 + l * 8 + p * 2 + 0];
        const float oy = oa[(size_t)q * 384 + h * 32 + l * 8 + p * 2 + 1];
        const float cx = ref[(size_t)q * 16 + l * 4 + 0];
        const float cy = ref[(size_t)q * 16 + l * 4 + 1];
        const float rw = ref[(size_t)q * 16 + l * 4 + 2];
        const float rh = ref[(size_t)q * 16 + l * 4 + 3];
        const int H = c_H[l], W = c_W[l];
        const int start = c_start[l];

        const float x = (cx + ox * 0.125f * rw) * (float)W - 0.5f;
        const float y = (cy + oy * 0.125f * rh) * (float)H - 0.5f;
        const float x0f = floorf(x), y0f = floorf(y);
        const int x0 = (int)x0f, y0 = (int)y0f;
        const float wx1 = x - x0f, wy1 = y - y0f;
        const float wx0 = 1.0f - wx1, wy0 = 1.0f - wy1;

        const bool vx0 = (x0 >= 0) && (x0 < W);
        const bool vx1 = (x0 + 1 >= 0) && (x0 + 1 < W);
        const bool vy0 = (y0 >= 0) && (y0 < H);
        const bool vy1 = (y0 + 1 >= 0) && (y0 + 1 < H);

        const int xc0 = min(max(x0, 0), W - 1);
        const int xc1 = min(max(x0 + 1, 0), W - 1);
        const int yc0 = min(max(y0, 0), H - 1);
        const int yc1 = min(max(y0 + 1, 0), H - 1);

        const int hb = h * 32;
        const int r0 = (start + yc0 * W) * CDIM + hb;
        const int r1 = (start + yc1 * W) * CDIM + hb;
        const int b = tid * 4;
        s_meta[b + 0] = make_int2(r0 + xc0 * CDIM,
            __float_as_int((vy0 && vx0) ? wn * wy0 * wx0 : 0.0f));
        s_meta[b + 1] = make_int2(r0 + xc1 * CDIM,
            __float_as_int((vy0 && vx1) ? wn * wy0 * wx1 : 0.0f));
        s_meta[b + 2] = make_int2(r1 + xc0 * CDIM,
            __float_as_int((vy1 && vx0) ? wn * wy1 * wx0 : 0.0f));
        s_meta[b + 3] = make_int2(r1 + xc1 * CDIM,
            __float_as_int((vy1 && vx1) ? wn * wy1 * wx1 : 0.0f));
    }
    __syncthreads();

    // ---- Phase 2: gather ----
    const int h    = tid >> 5;
    const int lane = tid & 31;
    const int cg   = lane >> 3;
    const int sc   = (lane & 7) * 4;
    const float* vp = v + sc;

    float4 acc = make_float4(0.f, 0.f, 0.f, 0.f);
    const int2* mp = &s_meta[h * 64 + cg];

    #pragma unroll
    for (int pt = 0; pt < 16; pt++) {
        const int2  m = mp[pt * 4];
        const float w = __int_as_float(m.y);
        const float4 vv = *reinterpret_cast<const float4*>(vp + m.x);
        acc.x = fmaf(w, vv.x, acc.x);
        acc.y = fmaf(w, vv.y, acc.y);
        acc.z = fmaf(w, vv.z, acc.z);
        acc.w = fmaf(w, vv.w, acc.w);
    }

    #pragma unroll
    for (int m = 8; m <= 16; m <<= 1) {
        acc.x += __shfl_xor_sync(~0u, acc.x, m);
        acc.y += __shfl_xor_sync(~0u, acc.y, m);
        acc.z += __shfl_xor_sync(~0u, acc.z, m);
        acc.w += __shfl_xor_sync(~0u, acc.w, m);
    }
    if (lane < 8) {
        __nv_bfloat162 h01 = __floats2bfloat162_rn(acc.x, acc.y);
        __nv_bfloat162 h23 = __floats2bfloat162_rn(acc.z, acc.w);
        __nv_bfloat162 l01 = __floats2bfloat162_rn(
            acc.x - __bfloat162float(h01.x), acc.y - __bfloat162float(h01.y));
        __nv_bfloat162 l23 = __floats2bfloat162_rn(
            acc.z - __bfloat162float(h23.x), acc.w - __bfloat162float(h23.y));
        uint2 hu, lu;
        hu.x = *reinterpret_cast<uint32_t*>(&h01);
        hu.y = *reinterpret_cast<uint32_t*>(&h23);
        lu.x = *reinterpret_cast<uint32_t*>(&l01);
        lu.y = *reinterpret_cast<uint32_t*>(&l23);
        const size_t o = (size_t)q * CDIM + h * 32 + sc;
        *reinterpret_cast<uint2*>(&g_amh[o]) = hu;
        *reinterpret_cast<uint2*>(&g_aml[o]) = lu;
    }
}

// ---------------------------------------------------------------------------
// Launch
// ---------------------------------------------------------------------------
extern "C" void kernel_launch(void* const* d_in, const int* in_sizes, int n_in,
                              void* d_out, int out_size)
{
    const float* query  = (const float*)d_in[0];
    const float* ref    = (const float*)d_in[1];
    const float* value  = (const float*)d_in[2];
    const float* W_off  = (const float*)d_in[3];
    const float* b_off  = (const float*)d_in[4];
    const float* W_attn = (const float*)d_in[5];
    const float* b_attn = (const float*)d_in[6];
    const float* W_val  = (const float*)d_in[7];
    const float* b_val  = (const float*)d_in[8];
    const float* W_out  = (const float*)d_in[9];
    const float* b_out  = (const float*)d_in[10];
    float* out = (float*)d_out;

    float *gv, *goa;
    __nv_bfloat16 *wh, *wl, *avh, *avl, *aqh, *aql;
    cudaGetSymbolAddress((void**)&gv,  g_v);
    cudaGetSymbolAddress((void**)&goa, g_oa);
    cudaGetSymbolAddress((void**)&wh,  g_wh);
    cudaGetSymbolAddress((void**)&wl,  g_wl);
    cudaGetSymbolAddress((void**)&avh, g_avh);
    cudaGetSymbolAddress((void**)&avl, g_avl);
    cudaGetSymbolAddress((void**)&aqh, g_aqh);
    cudaGetSymbolAddress((void**)&aql, g_aql);

    cudaFuncSetAttribute(gemm_front, cudaFuncAttributeMaxDynamicSharedMemorySize,
                         SM_TOTAL);
    cudaFuncSetAttribute(gemm_out, cudaFuncAttributeMaxDynamicSharedMemorySize,
                         SM_TOTAL);

    const int MT = LQP / 128;   // 174

    // 0. prep: weight split + A split (value, query)
    prep_all_w<<<(W_TOTAL + 255) / 256, 256>>>(W_val, W_off, W_attn, W_out, wh, wl);
    split_av<<<(2 * LQ * 64 + 255) / 256, 256>>>(value, query, avh, avl, aqh, aql);

    // 1. merged front GEMMs
    gemm_front<<<dim3(MT, 10), 256, SM_TOTAL>>>(wh, wl, b_val, b_off, b_attn,
                                                gv, goa);
    // 2. sampling (softmax fused; emits mid hi/lo bf16)
    sample_kernel<<<LQ, 256>>>(gv, goa, ref);
    // 3. out = mid @ W_out + b_out
    gemm_out<<<dim3(MT, 4), 256, SM_TOTAL>>>(wh, wl, b_out, out);
}

// round 13
// speedup vs baseline: 1.3226x; 1.0681x over previous
#include <cuda_runtime.h>
#include <cuda_bf16.h>
#include <cstdint>

// ---------------------------------------------------------------------------
// Problem constants
// ---------------------------------------------------------------------------
#define LQ      22223
#define LQP     22272                 // padded to 174*128
#define CDIM    256
#define NHEADS  8
#define NLVL    4
#define NPTS    4
#define KDIM    256

__device__ __constant__ int c_H[NLVL]     = {100, 50, 25, 13};
__device__ __constant__ int c_W[NLVL]     = {167, 84, 42, 21};
__device__ __constant__ int c_start[NLVL] = {0, 16700, 20900, 21950};

// ---------------------------------------------------------------------------
// Scratch (device globals; zero-initialized at module load — pad rows stay 0)
// ---------------------------------------------------------------------------
__device__ float g_v   [LQP * CDIM];  // value @ W_val + b_val (fp32, for gather)
__device__ float g_oa  [LQP * 384];   // [off(256) | attn logits(128)] per row

__device__ __nv_bfloat16 g_avh[LQP * CDIM];  // value split hi
__device__ __nv_bfloat16 g_avl[LQP * CDIM];  // value split lo
__device__ __nv_bfloat16 g_aqh[LQP * CDIM];  // query split hi
__device__ __nv_bfloat16 g_aql[LQP * CDIM];  // query split lo
__device__ __nv_bfloat16 g_amh[LQP * CDIM];  // mid   split hi (from sampler)
__device__ __nv_bfloat16 g_aml[LQP * CDIM];  // mid   split lo

// Weight splits, transposed to [N,K], packed: WVAL | WOFF | WATTN | WOUT
#define W_VAL_OFF   0
#define W_OFF_OFF   (256 * 256)
#define W_ATTN_OFF  (2 * 256 * 256)
#define W_OUT_OFF   (2 * 256 * 256 + 128 * 256)
#define W_TOTAL     (3 * 256 * 256 + 128 * 256)
__device__ __nv_bfloat16 g_wh[W_TOTAL];
__device__ __nv_bfloat16 g_wl[W_TOTAL];

// ---------------------------------------------------------------------------
// mma.sync / ldmatrix / cp.async helpers (plain sm_103)
// ---------------------------------------------------------------------------
__device__ __forceinline__ uint32_t smem_u32(const void* p) {
    uint32_t a;
    asm("{ .reg .u64 t; cvta.to.shared.u64 t, %1; cvt.u32.u64 %0, t; }"
        : "=r"(a) : "l"(p));
    return a;
}
__device__ __forceinline__ void ldsm_x4(uint32_t* r, uint32_t addr) {
    asm volatile("ldmatrix.sync.aligned.m8n8.x4.shared.b16 {%0,%1,%2,%3}, [%4];"
                 : "=r"(r[0]), "=r"(r[1]), "=r"(r[2]), "=r"(r[3]) : "r"(addr));
}
__device__ __forceinline__ void mma_bf16(float* d, const uint32_t* a,
                                         const uint32_t* b) {
    asm volatile(
        "mma.sync.aligned.m16n8k16.row.col.f32.bf16.bf16.f32 "
        "{%0,%1,%2,%3}, {%4,%5,%6,%7}, {%8,%9}, {%0,%1,%2,%3};"
        : "+f"(d[0]), "+f"(d[1]), "+f"(d[2]), "+f"(d[3])
        : "r"(a[0]), "r"(a[1]), "r"(a[2]), "r"(a[3]), "r"(b[0]), "r"(b[1]));
}
__device__ __forceinline__ void cp16(uint32_t dst, const void* src) {
    asm volatile("cp.async.cg.shared.global [%0], [%1], 16;"
                 :: "r"(dst), "l"(src) : "memory");
}
#define CP_COMMIT() asm volatile("cp.async.commit_group;" ::: "memory")
#define CP_WAIT0()  asm volatile("cp.async.wait_group 0;" ::: "memory")

// ---------------------------------------------------------------------------
// Prep: split all four fp32 W[K,N] into bf16 hi/lo at [N,K].
// ---------------------------------------------------------------------------
__global__ void prep_all_w(const float* __restrict__ Wv,
                           const float* __restrict__ Wo,
                           const float* __restrict__ Wa,
                           const float* __restrict__ Wu,
                           __nv_bfloat16* __restrict__ wh,
                           __nv_bfloat16* __restrict__ wl)
{
    int i = blockIdx.x * blockDim.x + threadIdx.x;
    if (i >= W_TOTAL) return;
    const float* W;
    int N, local, base;
    if (i < 65536)        { W = Wv; N = 256; base = W_VAL_OFF;  local = i; }
    else if (i < 131072)  { W = Wo; N = 256; base = W_OFF_OFF;  local = i - 65536; }
    else if (i < 163840)  { W = Wa; N = 128; base = W_ATTN_OFF; local = i - 131072; }
    else                  { W = Wu; N = 256; base = W_OUT_OFF;  local = i - 163840; }
    int k = local / N;
    int n = local - k * N;
    float a = W[(size_t)k * N + n];
    __nv_bfloat16 hi = __float2bfloat16(a);
    __nv_bfloat16 lo = __float2bfloat16(a - __bfloat162float(hi));
    wh[(size_t)base + (size_t)n * KDIM + k] = hi;
    wl[(size_t)base + (size_t)n * KDIM + k] = lo;
}

// Split value+query (fp32 [LQ,256]) into bf16 hi/lo.
__global__ void split_av(const float* __restrict__ value,
                         const float* __restrict__ query)
{
    const int n4 = LQ * 64;            // float4 count per tensor
    int i = blockIdx.x * blockDim.x + threadIdx.x;
    if (i >= 2 * n4) return;
    const float* src;
    __nv_bfloat16 *dh, *dl;
    int j;
    if (i < n4) { src = value; dh = g_avh; dl = g_avl; j = i; }
    else        { src = query; dh = g_aqh; dl = g_aql; j = i - n4; }
    float4 v = *reinterpret_cast<const float4*>(src + (size_t)j * 4);
    __nv_bfloat162 h01 = __floats2bfloat162_rn(v.x, v.y);
    __nv_bfloat162 h23 = __floats2bfloat162_rn(v.z, v.w);
    __nv_bfloat162 l01 = __floats2bfloat162_rn(
        v.x - __bfloat162float(h01.x), v.y - __bfloat162float(h01.y));
    __nv_bfloat162 l23 = __floats2bfloat162_rn(
        v.z - __bfloat162float(h23.x), v.w - __bfloat162float(h23.y));
    uint2 hu, lu;
    hu.x = *reinterpret_cast<uint32_t*>(&h01);
    hu.y = *reinterpret_cast<uint32_t*>(&h23);
    lu.x = *reinterpret_cast<uint32_t*>(&l01);
    lu.y = *reinterpret_cast<uint32_t*>(&l23);
    *reinterpret_cast<uint2*>(dh + (size_t)j * 4) = hu;
    *reinterpret_cast<uint2*>(dl + (size_t)j * 4) = lu;
}

// ---------------------------------------------------------------------------
// Split-bf16 mma.sync GEMM core. BM=128, BN=128, warp tile 32x64 (8 warps:
// 4m x 2n). K in two 128-chunks (SMEM 139KB). cp.async prologue.
// Pass order per K-step: (AhBh, AlBh) with Bh frags, then reload Bl -> AhBl.
// ---------------------------------------------------------------------------
#define LDK2  136
#define SM_AH 0
#define SM_AL (128 * LDK2 * 2)           //  34816
#define SM_BH (2 * 128 * LDK2 * 2)       //  69632
#define SM_BL (SM_BH + 128 * LDK2 * 2)   // 104448
#define SM_TOTAL (SM_BL + 128 * LDK2 * 2)// 139264

__device__ __forceinline__ void gemm_core(
    const __nv_bfloat16* __restrict__ ah,   // A hi [LQP, 256]
    const __nv_bfloat16* __restrict__ al,
    const __nv_bfloat16* __restrict__ bh,   // B hi for this col-tile [128, K]
    const __nv_bfloat16* __restrict__ bl,
    const float* __restrict__ bias0,
    const float* __restrict__ bias1,
    int nsplit, int col0,
    float* __restrict__ C, int M, int N, int m0, char* smem)
{
    const int tid  = threadIdx.x;
    const int wid  = tid >> 5;
    const int lane = tid & 31;
    const int warp_m = wid & 3;     // 32 rows
    const int warp_n = wid >> 2;    // 0..1, 64 cols

    const uint32_t sAh = smem_u32(smem + SM_AH);
    const uint32_t sAl = smem_u32(smem + SM_AL);
    const uint32_t sBh = smem_u32(smem + SM_BH);
    const uint32_t sBl = smem_u32(smem + SM_BL);

    float acc[2][8][4];
    #pragma unroll
    for (int i = 0; i < 2; i++)
        #pragma unroll
        for (int j = 0; j < 8; j++)
            #pragma unroll
            for (int k = 0; k < 4; k++) acc[i][j][k] = 0.0f;

    const int a_row  = warp_m * 32 + (lane & 15);
    const int a_colb = (lane >> 4) << 3;
    const int b_row  = warp_n * 64 + (lane & 7) + ((lane >> 4) << 3);
    const int b_colb = ((lane >> 3) & 1) << 3;

    #pragma unroll 1
    for (int chunk = 0; chunk < 2; ++chunk) {
        const int k0 = chunk << 7;
        if (chunk) __syncthreads();   // prior mainloop must finish before refill

        // ---- prologue: pure async copies (A padded -> no guards) ----
        #pragma unroll
        for (int i = 0; i < 8; i++) {
            const int idx = tid + (i << 8);
            const int r  = idx >> 4;             // 0..127
            const int ce = (idx & 15) << 3;      // 0..120 elems
            const uint32_t so = (uint32_t)((r * LDK2 + ce) * 2);
            const size_t ga = (size_t)(m0 + r) * CDIM + k0 + ce;
            const size_t gb = (size_t)r * KDIM + k0 + ce;
            cp16(sAh + so, ah + ga);
            cp16(sAl + so, al + ga);
            cp16(sBh + so, bh + gb);
            cp16(sBl + so, bl + gb);
        }
        CP_COMMIT();
        CP_WAIT0();
        __syncthreads();

        // ---- mainloop: 8 K-steps ----
        #pragma unroll
        for (int ks = 0; ks < 8; ks++) {
            const int kc = ks << 4;
            uint32_t fah[2][4], fal[2][4], fb[4][4];
            #pragma unroll
            for (int mt = 0; mt < 2; mt++) {
                const uint32_t off =
                    (uint32_t)(((a_row + mt * 16) * LDK2 + kc + a_colb) * 2);
                ldsm_x4(fah[mt], sAh + off);
                ldsm_x4(fal[mt], sAl + off);
            }
            #pragma unroll
            for (int np = 0; np < 4; np++) {
                const uint32_t off =
                    (uint32_t)(((b_row + np * 16) * LDK2 + kc + b_colb) * 2);
                ldsm_x4(fb[np], sBh + off);
            }
            #pragma unroll
            for (int mt = 0; mt < 2; mt++)
                #pragma unroll
                for (int nt = 0; nt < 8; nt++)
                    mma_bf16(acc[mt][nt], fah[mt], &fb[nt >> 1][(nt & 1) * 2]);
            #pragma unroll
            for (int mt = 0; mt < 2; mt++)
                #pragma unroll
                for (int nt = 0; nt < 8; nt++)
                    mma_bf16(acc[mt][nt], fal[mt], &fb[nt >> 1][(nt & 1) * 2]);
            #pragma unroll
            for (int np = 0; np < 4; np++) {
                const uint32_t off =
                    (uint32_t)(((b_row + np * 16) * LDK2 + kc + b_colb) * 2);
                ldsm_x4(fb[np], sBl + off);
            }
            #pragma unroll
            for (int mt = 0; mt < 2; mt++)
                #pragma unroll
                for (int nt = 0; nt < 8; nt++)
                    mma_bf16(acc[mt][nt], fah[mt], &fb[nt >> 1][(nt & 1) * 2]);
        }
    }

    // ---- epilogue ----
    const int er = lane >> 2;
    const int ec = (lane & 3) << 1;
    #pragma unroll
    for (int mt = 0; mt < 2; mt++) {
        #pragma unroll
        for (int nt = 0; nt < 8; nt++) {
            const int col = col0 + warp_n * 64 + nt * 8 + ec;
            const float b0 = (col < nsplit)     ? bias0[col]     : bias1[col - nsplit];
            const float b1 = (col + 1 < nsplit) ? bias0[col + 1] : bias1[col + 1 - nsplit];
            const int r0 = m0 + warp_m * 32 + mt * 16 + er;
            if (r0 < M) {
                float2 o = make_float2(acc[mt][nt][0] + b0, acc[mt][nt][1] + b1);
                *reinterpret_cast<float2*>(&C[(size_t)r0 * N + col]) = o;
            }
            if (r0 + 8 < M) {
                float2 o = make_float2(acc[mt][nt][2] + b0, acc[mt][nt][3] + b1);
                *reinterpret_cast<float2*>(&C[(size_t)(r0 + 8) * N + col]) = o;
            }
        }
    }
}

// Merged front GEMM: grid.y 0..1 -> value GEMM (N=256, col0 = y*128, C=g_v),
//                    grid.y 2..4 -> query GEMM (N=384, C=g_oa, bias split 256)
__global__ __launch_bounds__(256)
void gemm_front(const __nv_bfloat16* __restrict__ wh,
                const __nv_bfloat16* __restrict__ wl,
                const float* __restrict__ b_val,
                const float* __restrict__ b_off,
                const float* __restrict__ b_attn,
                float* __restrict__ Cv, float* __restrict__ Coa)
{
    extern __shared__ __align__(16) char smem[];
    const int y = blockIdx.y;
    const int m0 = blockIdx.x * 128;
    if (y < 2) {
        const int col0 = y * 128;
        gemm_core(g_avh, g_avl,
                  wh + W_VAL_OFF + (size_t)col0 * KDIM,
                  wl + W_VAL_OFF + (size_t)col0 * KDIM,
                  b_val, b_val, 1 << 30, col0, Cv, LQP, 256, m0, smem);
    } else {
        const int col0 = (y - 2) * 128;
        gemm_core(g_aqh, g_aql,
                  wh + W_OFF_OFF + (size_t)col0 * KDIM,
                  wl + W_OFF_OFF + (size_t)col0 * KDIM,
                  b_off, b_attn, 256, col0, Coa, LQP, 384, m0, smem);
    }
}

// Output GEMM (A = mid hi/lo produced by sampler)
__global__ __launch_bounds__(256)
void gemm_out(const __nv_bfloat16* __restrict__ wh,
              const __nv_bfloat16* __restrict__ wl,
              const float* __restrict__ b_out,
              float* __restrict__ C)
{
    extern __shared__ __align__(16) char smem[];
    const int col0 = blockIdx.y * 128;
    gemm_core(g_amh, g_aml,
              wh + W_OUT_OFF + (size_t)col0 * KDIM,
              wl + W_OUT_OFF + (size_t)col0 * KDIM,
              b_out, b_out, 1 << 30, col0, C, LQ, 256, blockIdx.x * 128, smem);
}

// ---------------------------------------------------------------------------
// Sampling: 2 queries per block. Phase 1: 256 threads = 2x128 points.
// Phase 2: warp = head, two sequential (q,h) gather tasks.
// Emits mid as bf16 hi/lo directly.
// ---------------------------------------------------------------------------
__global__ __launch_bounds__(256) void sample_kernel(
    const float* __restrict__ v, const float* __restrict__ oa,
    const float* __restrict__ ref)
{
    __shared__ int2 s_meta[2][512];    // [t][(h*16+pt)*4 + corner]

    const int q0  = blockIdx.x * 2;
    const int tid = threadIdx.x;

    // ---- Phase 1: all 256 threads (t = tid>>7 selects query) ----
    {
        const int t    = tid >> 7;
        const int tl   = tid & 127;
        const int q    = q0 + t;
        if (q < LQ) {
            const int h  = tl >> 4;
            const int l  = (tl >> 2) & 3;
            const int p  = tl & 3;

            float lg = oa[(size_t)q * 384 + 256 + h * 16 + l * 4 + p];
            float mx = lg;
            #pragma unroll
            for (int m = 8; m; m >>= 1) mx = fmaxf(mx, __shfl_xor_sync(~0u, mx, m));
            float ex = __expf(lg - mx);
            float sm = ex;
            #pragma unroll
            for (int m = 8; m; m >>= 1) sm += __shfl_xor_sync(~0u, sm, m);
            const float wn = ex / sm;

            const float ox = oa[(size_t)q * 384 + h * 32 + l * 8 + p * 2 + 0];
            const float oy = oa[(size_t)q * 384 + h * 32 + l * 8 + p * 2 + 1];
            const float cx = ref[(size_t)q * 16 + l * 4 + 0];
            const float cy = ref[(size_t)q * 16 + l * 4 + 1];
            const float rw = ref[(size_t)q * 16 + l * 4 + 2];
            const float rh = ref[(size_t)q * 16 + l * 4 + 3];
            const int H = c_H[l], W = c_W[l];
            const int start = c_start[l];

            const float x = (cx + ox * 0.125f * rw) * (float)W - 0.5f;
            const float y = (cy + oy * 0.125f * rh) * (float)H - 0.5f;
            const float x0f = floorf(x), y0f = floorf(y);
            const int x0 = (int)x0f, y0 = (int)y0f;
            const float wx1 = x - x0f, wy1 = y - y0f;
            const float wx0 = 1.0f - wx1, wy0 = 1.0f - wy1;

            const bool vx0 = (x0 >= 0) && (x0 < W);
            const bool vx1 = (x0 + 1 >= 0) && (x0 + 1 < W);
            const bool vy0 = (y0 >= 0) && (y0 < H);
            const bool vy1 = (y0 + 1 >= 0) && (y0 + 1 < H);

            const int xc0 = min(max(x0, 0), W - 1);
            const int xc1 = min(max(x0 + 1, 0), W - 1);
            const int yc0 = min(max(y0, 0), H - 1);
            const int yc1 = min(max(y0 + 1, 0), H - 1);

            const int hb = h * 32;
            const int r0 = (start + yc0 * W) * CDIM + hb;
            const int r1 = (start + yc1 * W) * CDIM + hb;
            const int b = tl * 4;
            s_meta[t][b + 0] = make_int2(r0 + xc0 * CDIM,
                __float_as_int((vy0 && vx0) ? wn * wy0 * wx0 : 0.0f));
            s_meta[t][b + 1] = make_int2(r0 + xc1 * CDIM,
                __float_as_int((vy0 && vx1) ? wn * wy0 * wx1 : 0.0f));
            s_meta[t][b + 2] = make_int2(r1 + xc0 * CDIM,
                __float_as_int((vy1 && vx0) ? wn * wy1 * wx0 : 0.0f));
            s_meta[t][b + 3] = make_int2(r1 + xc1 * CDIM,
                __float_as_int((vy1 && vx1) ? wn * wy1 * wx1 : 0.0f));
        }
    }
    __syncthreads();

    // ---- Phase 2: gather; warp = head, loop over the block's 2 queries ----
    const int h    = tid >> 5;
    const int lane = tid & 31;
    const int cg   = lane >> 3;
    const int sc   = (lane & 7) * 4;
    const float* vp = v + sc;

    #pragma unroll
    for (int t = 0; t < 2; t++) {
        const int q = q0 + t;
        if (q >= LQ) break;
        float4 acc = make_float4(0.f, 0.f, 0.f, 0.f);
        const int2* mp = &s_meta[t][h * 64 + cg];

        #pragma unroll
        for (int pt = 0; pt < 16; pt++) {
            const int2  m = mp[pt * 4];
            const float w = __int_as_float(m.y);
            const float4 vv = *reinterpret_cast<const float4*>(vp + m.x);
            acc.x = fmaf(w, vv.x, acc.x);
            acc.y = fmaf(w, vv.y, acc.y);
            acc.z = fmaf(w, vv.z, acc.z);
            acc.w = fmaf(w, vv.w, acc.w);
        }

        #pragma unroll
        for (int m = 8; m <= 16; m <<= 1) {
            acc.x += __shfl_xor_sync(~0u, acc.x, m);
            acc.y += __shfl_xor_sync(~0u, acc.y, m);
            acc.z += __shfl_xor_sync(~0u, acc.z, m);
            acc.w += __shfl_xor_sync(~0u, acc.w, m);
        }
        if (lane < 8) {
            __nv_bfloat162 h01 = __floats2bfloat162_rn(acc.x, acc.y);
            __nv_bfloat162 h23 = __floats2bfloat162_rn(acc.z, acc.w);
            __nv_bfloat162 l01 = __floats2bfloat162_rn(
                acc.x - __bfloat162float(h01.x), acc.y - __bfloat162float(h01.y));
            __nv_bfloat162 l23 = __floats2bfloat162_rn(
                acc.z - __bfloat162float(h23.x), acc.w - __bfloat162float(h23.y));
            uint2 hu, lu;
            hu.x = *reinterpret_cast<uint32_t*>(&h01);
            hu.y = *reinterpret_cast<uint32_t*>(&h23);
            lu.x = *reinterpret_cast<uint32_t*>(&l01);
            lu.y = *reinterpret_cast<uint32_t*>(&l23);
            const size_t o = (size_t)q * CDIM + h * 32 + sc;
            *reinterpret_cast<uint2*>(&g_amh[o]) = hu;
            *reinterpret_cast<uint2*>(&g_aml[o]) = lu;
        }
    }
}

// ---------------------------------------------------------------------------
// Launch
// ---------------------------------------------------------------------------
extern "C" void kernel_launch(void* const* d_in, const int* in_sizes, int n_in,
                              void* d_out, int out_size)
{
    const float* query  = (const float*)d_in[0];
    const float* ref    = (const float*)d_in[1];
    const float* value  = (const float*)d_in[2];
    const float* W_off  = (const float*)d_in[3];
    const float* b_off  = (const float*)d_in[4];
    const float* W_attn = (const float*)d_in[5];
    const float* b_attn = (const float*)d_in[6];
    const float* W_val  = (const float*)d_in[7];
    const float* b_val  = (const float*)d_in[8];
    const float* W_out  = (const float*)d_in[9];
    const float* b_out  = (const float*)d_in[10];
    float* out = (float*)d_out;

    float *gv, *goa;
    __nv_bfloat16 *wh, *wl;
    cudaGetSymbolAddress((void**)&gv,  g_v);
    cudaGetSymbolAddress((void**)&goa, g_oa);
    cudaGetSymbolAddress((void**)&wh,  g_wh);
    cudaGetSymbolAddress((void**)&wl,  g_wl);

    cudaFuncSetAttribute(gemm_front, cudaFuncAttributeMaxDynamicSharedMemorySize,
                         SM_TOTAL);
    cudaFuncSetAttribute(gemm_out, cudaFuncAttributeMaxDynamicSharedMemorySize,
                         SM_TOTAL);

    const int MT = LQP / 128;   // 174

    // 0. prep: weight split + A split (value, query)
    prep_all_w<<<(W_TOTAL + 255) / 256, 256>>>(W_val, W_off, W_attn, W_out, wh, wl);
    split_av<<<(2 * LQ * 64 + 255) / 256, 256>>>(value, query);

    // 1. merged front GEMMs: y 0..1 value (N=256), y 2..4 query (N=384)
    gemm_front<<<dim3(MT, 5), 256, SM_TOTAL>>>(wh, wl, b_val, b_off, b_attn,
                                               gv, goa);
    // 2. sampling (softmax fused; 2 queries per block; emits mid hi/lo bf16)
    sample_kernel<<<(LQ + 1) / 2, 256>>>(gv, goa, ref);
    // 3. out = mid @ W_out + b_out
    gemm_out<<<dim3(MT, 2), 256, SM_TOTAL>>>(wh, wl, b_out, out);
}

// round 15
// speedup vs baseline: 1.3506x; 1.0212x over previous
#include <cuda_runtime.h>
#include <cuda_bf16.h>
#include <cstdint>

// ---------------------------------------------------------------------------
// Problem constants
// ---------------------------------------------------------------------------
#define LQ      22223
#define LQP     22272                 // padded to 174*128
#define CDIM    256
#define NHEADS  8
#define NLVL    4
#define NPTS    4
#define KDIM    256

__device__ __constant__ int c_H[NLVL]     = {100, 50, 25, 13};
__device__ __constant__ int c_W[NLVL]     = {167, 84, 42, 21};
__device__ __constant__ int c_start[NLVL] = {0, 16700, 20900, 21950};

// ---------------------------------------------------------------------------
// Scratch (device globals; zero-initialized at module load — pad rows stay 0)
// ---------------------------------------------------------------------------
__device__ float g_v   [LQP * CDIM];  // value @ W_val + b_val (fp32, for gather)
__device__ float g_oa  [LQP * 384];   // [off(256) | attn logits(128)] per row

__device__ __nv_bfloat16 g_avh[LQP * CDIM];  // value split hi
__device__ __nv_bfloat16 g_avl[LQP * CDIM];  // value split lo
__device__ __nv_bfloat16 g_aqh[LQP * CDIM];  // query split hi
__device__ __nv_bfloat16 g_aql[LQP * CDIM];  // query split lo
__device__ __nv_bfloat16 g_amh[LQP * CDIM];  // mid   split hi (from sampler)
__device__ __nv_bfloat16 g_aml[LQP * CDIM];  // mid   split lo

// Weight splits, transposed to [N,K], packed: WVAL | WOFF | WATTN | WOUT
#define W_VAL_OFF   0
#define W_OFF_OFF   (256 * 256)
#define W_ATTN_OFF  (2 * 256 * 256)
#define W_OUT_OFF   (2 * 256 * 256 + 128 * 256)
#define W_TOTAL     (3 * 256 * 256 + 128 * 256)
__device__ __nv_bfloat16 g_wh[W_TOTAL];
__device__ __nv_bfloat16 g_wl[W_TOTAL];

// ---------------------------------------------------------------------------
// mma.sync / ldmatrix / cp.async helpers (plain sm_103)
// ---------------------------------------------------------------------------
__device__ __forceinline__ uint32_t smem_u32(const void* p) {
    uint32_t a;
    asm("{ .reg .u64 t; cvta.to.shared.u64 t, %1; cvt.u32.u64 %0, t; }"
        : "=r"(a) : "l"(p));
    return a;
}
__device__ __forceinline__ void ldsm_x4(uint32_t* r, uint32_t addr) {
    asm volatile("ldmatrix.sync.aligned.m8n8.x4.shared.b16 {%0,%1,%2,%3}, [%4];"
                 : "=r"(r[0]), "=r"(r[1]), "=r"(r[2]), "=r"(r[3]) : "r"(addr));
}
__device__ __forceinline__ void mma_bf16(float* d, const uint32_t* a,
                                         const uint32_t* b) {
    asm volatile(
        "mma.sync.aligned.m16n8k16.row.col.f32.bf16.bf16.f32 "
        "{%0,%1,%2,%3}, {%4,%5,%6,%7}, {%8,%9}, {%0,%1,%2,%3};"
        : "+f"(d[0]), "+f"(d[1]), "+f"(d[2]), "+f"(d[3])
        : "r"(a[0]), "r"(a[1]), "r"(a[2]), "r"(a[3]), "r"(b[0]), "r"(b[1]));
}
__device__ __forceinline__ void cp16(uint32_t dst, const void* src) {
    asm volatile("cp.async.cg.shared.global [%0], [%1], 16;"
                 :: "r"(dst), "l"(src) : "memory");
}
#define CP_COMMIT() asm volatile("cp.async.commit_group;" ::: "memory")
#define CP_WAIT(n)  asm volatile("cp.async.wait_group %0;" :: "n"(n) : "memory")

// ---------------------------------------------------------------------------
// Prep: split all four fp32 W[K,N] into bf16 hi/lo at [N,K].
// ---------------------------------------------------------------------------
__global__ void prep_all_w(const float* __restrict__ Wv,
                           const float* __restrict__ Wo,
                           const float* __restrict__ Wa,
                           const float* __restrict__ Wu,
                           __nv_bfloat16* __restrict__ wh,
                           __nv_bfloat16* __restrict__ wl)
{
    int i = blockIdx.x * blockDim.x + threadIdx.x;
    if (i >= W_TOTAL) return;
    const float* W;
    int N, local, base;
    if (i < 65536)        { W = Wv; N = 256; base = W_VAL_OFF;  local = i; }
    else if (i < 131072)  { W = Wo; N = 256; base = W_OFF_OFF;  local = i - 65536; }
    else if (i < 163840)  { W = Wa; N = 128; base = W_ATTN_OFF; local = i - 131072; }
    else                  { W = Wu; N = 256; base = W_OUT_OFF;  local = i - 163840; }
    int k = local / N;
    int n = local - k * N;
    float a = W[(size_t)k * N + n];
    __nv_bfloat16 hi = __float2bfloat16(a);
    __nv_bfloat16 lo = __float2bfloat16(a - __bfloat162float(hi));
    wh[(size_t)base + (size_t)n * KDIM + k] = hi;
    wl[(size_t)base + (size_t)n * KDIM + k] = lo;
}

// Split value+query (fp32 [LQ,256]) into bf16 hi/lo.
__global__ void split_av(const float* __restrict__ value,
                         const float* __restrict__ query)
{
    const int n4 = LQ * 64;            // float4 count per tensor
    int i = blockIdx.x * blockDim.x + threadIdx.x;
    if (i >= 2 * n4) return;
    const float* src;
    __nv_bfloat16 *dh, *dl;
    int j;
    if (i < n4) { src = value; dh = g_avh; dl = g_avl; j = i; }
    else        { src = query; dh = g_aqh; dl = g_aql; j = i - n4; }
    float4 v = *reinterpret_cast<const float4*>(src + (size_t)j * 4);
    __nv_bfloat162 h01 = __floats2bfloat162_rn(v.x, v.y);
    __nv_bfloat162 h23 = __floats2bfloat162_rn(v.z, v.w);
    __nv_bfloat162 l01 = __floats2bfloat162_rn(
        v.x - __bfloat162float(h01.x), v.y - __bfloat162float(h01.y));
    __nv_bfloat162 l23 = __floats2bfloat162_rn(
        v.z - __bfloat162float(h23.x), v.w - __bfloat162float(h23.y));
    uint2 hu, lu;
    hu.x = *reinterpret_cast<uint32_t*>(&h01);
    hu.y = *reinterpret_cast<uint32_t*>(&h23);
    lu.x = *reinterpret_cast<uint32_t*>(&l01);
    lu.y = *reinterpret_cast<uint32_t*>(&l23);
    *reinterpret_cast<uint2*>(dh + (size_t)j * 4) = hu;
    *reinterpret_cast<uint2*>(dl + (size_t)j * 4) = lu;
}

// ---------------------------------------------------------------------------
// Split-bf16 mma.sync GEMM core. BM=128, BN=128, warp tile 32x64 (8 warps).
// K in FOUR 64-chunks with a 2-stage cp.async pipeline (compute chunk c
// overlaps copy of chunk c+1). SMEM: 2 stages x 72KB = 144KB.
// ---------------------------------------------------------------------------
#define LDK64 72
#define ST_AH 0
#define ST_AL (128 * LDK64 * 2)            // 18432
#define ST_BH (2 * 128 * LDK64 * 2)        // 36864
#define ST_BL (ST_BH + 128 * LDK64 * 2)    // 55296
#define STAGE_SZ (4 * 128 * LDK64 * 2)     // 73728
#define SM_TOTAL (2 * STAGE_SZ)            // 147456

__device__ __forceinline__ void gemm_core(
    const __nv_bfloat16* __restrict__ ah,   // A hi [LQP, 256]
    const __nv_bfloat16* __restrict__ al,
    const __nv_bfloat16* __restrict__ bh,   // B hi for this col-tile [128, K]
    const __nv_bfloat16* __restrict__ bl,
    const float* __restrict__ bias0,
    const float* __restrict__ bias1,
    int nsplit, int col0,
    float* __restrict__ C, int M, int N, int m0, char* smem)
{
    const int tid  = threadIdx.x;
    const int wid  = tid >> 5;
    const int lane = tid & 31;
    const int warp_m = wid & 3;     // 32 rows
    const int warp_n = wid >> 2;    // 0..1, 64 cols

    const uint32_t sbase = smem_u32(smem);

    // prefetch mapping: 4 cp16 per thread per array per stage
    const int pr  = (tid << 2) >> 3;          // unused placeholder
    (void)pr;

    // issue one chunk's copies into stage s
    auto issue = [&](int s, int chunk) {
        const int k0 = chunk << 6;
        const uint32_t st = sbase + s * STAGE_SZ;
        #pragma unroll
        for (int i = 0; i < 4; i++) {
            const int idx = tid + (i << 8);       // 0..1023
            const int r  = idx >> 3;              // 0..127
            const int ce = (idx & 7) << 3;        // 0..56 elems
            const uint32_t so = (uint32_t)((r * LDK64 + ce) * 2);
            const size_t ga = (size_t)(m0 + r) * CDIM + k0 + ce;
            const size_t gb = (size_t)r * KDIM + k0 + ce;
            cp16(st + ST_AH + so, ah + ga);
            cp16(st + ST_AL + so, al + ga);
            cp16(st + ST_BH + so, bh + gb);
            cp16(st + ST_BL + so, bl + gb);
        }
        CP_COMMIT();
    };

    float acc[2][8][4];
    #pragma unroll
    for (int i = 0; i < 2; i++)
        #pragma unroll
        for (int j = 0; j < 8; j++)
            #pragma unroll
            for (int k = 0; k < 4; k++) acc[i][j][k] = 0.0f;

    const int a_row  = warp_m * 32 + (lane & 15);
    const int a_colb = (lane >> 4) << 3;
    const int b_row  = warp_n * 64 + (lane & 7) + ((lane >> 4) << 3);
    const int b_colb = ((lane >> 3) & 1) << 3;

    issue(0, 0);

    #pragma unroll 1
    for (int c = 0; c < 4; ++c) {
        const int s = c & 1;
        if (c < 3) issue(s ^ 1, c + 1);
        if (c < 3) { CP_WAIT(1); } else { CP_WAIT(0); }
        __syncthreads();

        const uint32_t st = sbase + s * STAGE_SZ;
        const uint32_t sAh = st + ST_AH, sAl = st + ST_AL;
        const uint32_t sBh = st + ST_BH, sBl = st + ST_BL;

        #pragma unroll
        for (int ks = 0; ks < 4; ks++) {
            const int kc = ks << 4;
            uint32_t fah[2][4], fal[2][4], fb[4][4];
            #pragma unroll
            for (int mt = 0; mt < 2; mt++) {
                const uint32_t off =
                    (uint32_t)(((a_row + mt * 16) * LDK64 + kc + a_colb) * 2);
                ldsm_x4(fah[mt], sAh + off);
                ldsm_x4(fal[mt], sAl + off);
            }
            #pragma unroll
            for (int np = 0; np < 4; np++) {
                const uint32_t off =
                    (uint32_t)(((b_row + np * 16) * LDK64 + kc + b_colb) * 2);
                ldsm_x4(fb[np], sBh + off);
            }
            #pragma unroll
            for (int mt = 0; mt < 2; mt++)
                #pragma unroll
                for (int nt = 0; nt < 8; nt++)
                    mma_bf16(acc[mt][nt], fah[mt], &fb[nt >> 1][(nt & 1) * 2]);
            #pragma unroll
            for (int mt = 0; mt < 2; mt++)
                #pragma unroll
                for (int nt = 0; nt < 8; nt++)
                    mma_bf16(acc[mt][nt], fal[mt], &fb[nt >> 1][(nt & 1) * 2]);
            #pragma unroll
            for (int np = 0; np < 4; np++) {
                const uint32_t off =
                    (uint32_t)(((b_row + np * 16) * LDK64 + kc + b_colb) * 2);
                ldsm_x4(fb[np], sBl + off);
            }
            #pragma unroll
            for (int mt = 0; mt < 2; mt++)
                #pragma unroll
                for (int nt = 0; nt < 8; nt++)
                    mma_bf16(acc[mt][nt], fah[mt], &fb[nt >> 1][(nt & 1) * 2]);
        }
        __syncthreads();   // stage s free for reuse at c+2
    }

    // ---- epilogue ----
    const int er = lane >> 2;
    const int ec = (lane & 3) << 1;
    #pragma unroll
    for (int mt = 0; mt < 2; mt++) {
        #pragma unroll
        for (int nt = 0; nt < 8; nt++) {
            const int col = col0 + warp_n * 64 + nt * 8 + ec;
            const float b0 = (col < nsplit)     ? bias0[col]     : bias1[col - nsplit];
            const float b1 = (col + 1 < nsplit) ? bias0[col + 1] : bias1[col + 1 - nsplit];
            const int r0 = m0 + warp_m * 32 + mt * 16 + er;
            if (r0 < M) {
                float2 o = make_float2(acc[mt][nt][0] + b0, acc[mt][nt][1] + b1);
                *reinterpret_cast<float2*>(&C[(size_t)r0 * N + col]) = o;
            }
            if (r0 + 8 < M) {
                float2 o = make_float2(acc[mt][nt][2] + b0, acc[mt][nt][3] + b1);
                *reinterpret_cast<float2*>(&C[(size_t)(r0 + 8) * N + col]) = o;
            }
        }
    }
}

// Merged front GEMM: grid.y 0..1 -> value GEMM (N=256, col0 = y*128, C=g_v),
//                    grid.y 2..4 -> query GEMM (N=384, C=g_oa, bias split 256)
__global__ __launch_bounds__(256)
void gemm_front(const __nv_bfloat16* __restrict__ wh,
                const __nv_bfloat16* __restrict__ wl,
                const float* __restrict__ b_val,
                const float* __restrict__ b_off,
                const float* __restrict__ b_attn,
                float* __restrict__ Cv, float* __restrict__ Coa)
{
    extern __shared__ __align__(16) char smem[];
    const int y = blockIdx.y;
    const int m0 = blockIdx.x * 128;
    if (y < 2) {
        const int col0 = y * 128;
        gemm_core(g_avh, g_avl,
                  wh + W_VAL_OFF + (size_t)col0 * KDIM,
                  wl + W_VAL_OFF + (size_t)col0 * KDIM,
                  b_val, b_val, 1 << 30, col0, Cv, LQP, 256, m0, smem);
    } else {
        const int col0 = (y - 2) * 128;
        gemm_core(g_aqh, g_aql,
                  wh + W_OFF_OFF + (size_t)col0 * KDIM,
                  wl + W_OFF_OFF + (size_t)col0 * KDIM,
                  b_off, b_attn, 256, col0, Coa, LQP, 384, m0, smem);
    }
}

// Output GEMM (A = mid hi/lo produced by sampler)
__global__ __launch_bounds__(256)
void gemm_out(const __nv_bfloat16* __restrict__ wh,
              const __nv_bfloat16* __restrict__ wl,
              const float* __restrict__ b_out,
              float* __restrict__ C)
{
    extern __shared__ __align__(16) char smem[];
    const int col0 = blockIdx.y * 128;
    gemm_core(g_amh, g_aml,
              wh + W_OUT_OFF + (size_t)col0 * KDIM,
              wl + W_OUT_OFF + (size_t)col0 * KDIM,
              b_out, b_out, 1 << 30, col0, C, LQ, 256, blockIdx.x * 128, smem);
}

// ---------------------------------------------------------------------------
// Sampling: 2 queries per block; phase 2 interleaves both queries' gathers
// (dual accumulators -> 2x MLP). Emits mid as bf16 hi/lo.
// ---------------------------------------------------------------------------
__global__ __launch_bounds__(256) void sample_kernel(
    const float* __restrict__ v, const float* __restrict__ oa,
    const float* __restrict__ ref)
{
    __shared__ int2 s_meta[2][512];    // [t][(h*16+pt)*4 + corner]

    const int q0  = blockIdx.x * 2;
    const int tid = threadIdx.x;

    // ---- Phase 1: all 256 threads (t = tid>>7 selects query) ----
    {
        const int t    = tid >> 7;
        const int tl   = tid & 127;
        const int q    = q0 + t;
        const int b    = tl * 4;
        if (q < LQ) {
            const int h  = tl >> 4;
            const int l  = (tl >> 2) & 3;
            const int p  = tl & 3;

            float lg = oa[(size_t)q * 384 + 256 + h * 16 + l * 4 + p];
            float mx = lg;
            #pragma unroll
            for (int m = 8; m; m >>= 1) mx = fmaxf(mx, __shfl_xor_sync(~0u, mx, m));
            float ex = __expf(lg - mx);
            float sm = ex;
            #pragma unroll
            for (int m = 8; m; m >>= 1) sm += __shfl_xor_sync(~0u, sm, m);
            const float wn = ex / sm;

            const float ox = oa[(size_t)q * 384 + h * 32 + l * 8 + p * 2 + 0];
            const float oy = oa[(size_t)q * 384 + h * 32 + l * 8 + p * 2 + 1];
            const float cx = ref[(size_t)q * 16 + l * 4 + 0];
            const float cy = ref[(size_t)q * 16 + l * 4 + 1];
            const float rw = ref[(size_t)q * 16 + l * 4 + 2];
            const float rh = ref[(size_t)q * 16 + l * 4 + 3];
            const int H = c_H[l], W = c_W[l];
            const int start = c_start[l];

            const float x = (cx + ox * 0.125f * rw) * (float)W - 0.5f;
            const float y = (cy + oy * 0.125f * rh) * (float)H - 0.5f;
            const float x0f = floorf(x), y0f = floorf(y);
            const int x0 = (int)x0f, y0 = (int)y0f;
            const float wx1 = x - x0f, wy1 = y - y0f;
            const float wx0 = 1.0f - wx1, wy0 = 1.0f - wy1;

            const bool vx0 = (x0 >= 0) && (x0 < W);
            const bool vx1 = (x0 + 1 >= 0) && (x0 + 1 < W);
            const bool vy0 = (y0 >= 0) && (y0 < H);
            const bool vy1 = (y0 + 1 >= 0) && (y0 + 1 < H);

            const int xc0 = min(max(x0, 0), W - 1);
            const int xc1 = min(max(x0 + 1, 0), W - 1);
            const int yc0 = min(max(y0, 0), H - 1);
            const int yc1 = min(max(y0 + 1, 0), H - 1);

            const int hb = h * 32;
            const int r0 = (start + yc0 * W) * CDIM + hb;
            const int r1 = (start + yc1 * W) * CDIM + hb;
            s_meta[t][b + 0] = make_int2(r0 + xc0 * CDIM,
                __float_as_int((vy0 && vx0) ? wn * wy0 * wx0 : 0.0f));
            s_meta[t][b + 1] = make_int2(r0 + xc1 * CDIM,
                __float_as_int((vy0 && vx1) ? wn * wy0 * wx1 : 0.0f));
            s_meta[t][b + 2] = make_int2(r1 + xc0 * CDIM,
                __float_as_int((vy1 && vx0) ? wn * wy1 * wx0 : 0.0f));
            s_meta[t][b + 3] = make_int2(r1 + xc1 * CDIM,
                __float_as_int((vy1 && vx1) ? wn * wy1 * wx1 : 0.0f));
        } else {
            s_meta[t][b + 0] = make_int2(0, 0);
            s_meta[t][b + 1] = make_int2(0, 0);
            s_meta[t][b + 2] = make_int2(0, 0);
            s_meta[t][b + 3] = make_int2(0, 0);
        }
    }
    __syncthreads();

    // ---- Phase 2: interleaved gather for both queries ----
    const int h    = tid >> 5;
    const int lane = tid & 31;
    const int cg   = lane >> 3;
    const int sc   = (lane & 7) * 4;
    const float* vp = v + sc;

    float4 acc0 = make_float4(0.f, 0.f, 0.f, 0.f);
    float4 acc1 = make_float4(0.f, 0.f, 0.f, 0.f);
    const int2* mp0 = &s_meta[0][h * 64 + cg];
    const int2* mp1 = &s_meta[1][h * 64 + cg];

    #pragma unroll
    for (int pt = 0; pt < 16; pt++) {
        const int2  m0 = mp0[pt * 4];
        const int2  m1 = mp1[pt * 4];
        const float w0 = __int_as_float(m0.y);
        const float w1 = __int_as_float(m1.y);
        const float4 v0 = *reinterpret_cast<const float4*>(vp + m0.x);
        const float4 v1 = *reinterpret_cast<const float4*>(vp + m1.x);
        acc0.x = fmaf(w0, v0.x, acc0.x);
        acc0.y = fmaf(w0, v0.y, acc0.y);
        acc0.z = fmaf(w0, v0.z, acc0.z);
        acc0.w = fmaf(w0, v0.w, acc0.w);
        acc1.x = fmaf(w1, v1.x, acc1.x);
        acc1.y = fmaf(w1, v1.y, acc1.y);
        acc1.z = fmaf(w1, v1.z, acc1.z);
        acc1.w = fmaf(w1, v1.w, acc1.w);
    }

    #pragma unroll
    for (int m = 8; m <= 16; m <<= 1) {
        acc0.x += __shfl_xor_sync(~0u, acc0.x, m);
        acc0.y += __shfl_xor_sync(~0u, acc0.y, m);
        acc0.z += __shfl_xor_sync(~0u, acc0.z, m);
        acc0.w += __shfl_xor_sync(~0u, acc0.w, m);
        acc1.x += __shfl_xor_sync(~0u, acc1.x, m);
        acc1.y += __shfl_xor_sync(~0u, acc1.y, m);
        acc1.z += __shfl_xor_sync(~0u, acc1.z, m);
        acc1.w += __shfl_xor_sync(~0u, acc1.w, m);
    }
    if (lane < 8) {
        #pragma unroll
        for (int t = 0; t < 2; t++) {
            const int q = q0 + t;
            if (q >= LQ) break;
            const float4 acc = t ? acc1 : acc0;
            __nv_bfloat162 h01 = __floats2bfloat162_rn(acc.x, acc.y);
            __nv_bfloat162 h23 = __floats2bfloat162_rn(acc.z, acc.w);
            __nv_bfloat162 l01 = __floats2bfloat162_rn(
                acc.x - __bfloat162float(h01.x), acc.y - __bfloat162float(h01.y));
            __nv_bfloat162 l23 = __floats2bfloat162_rn(
                acc.z - __bfloat162float(h23.x), acc.w - __bfloat162float(h23.y));
            uint2 hu, lu;
            hu.x = *reinterpret_cast<uint32_t*>(&h01);
            hu.y = *reinterpret_cast<uint32_t*>(&h23);
            lu.x = *reinterpret_cast<uint32_t*>(&l01);
            lu.y = *reinterpret_cast<uint32_t*>(&l23);
            const size_t o = (size_t)q * CDIM + h * 32 + sc;
            *reinterpret_cast<uint2*>(&g_amh[o]) = hu;
            *reinterpret_cast<uint2*>(&g_aml[o]) = lu;
        }
    }
}

// ---------------------------------------------------------------------------
// Launch
// ---------------------------------------------------------------------------
extern "C" void kernel_launch(void* const* d_in, const int* in_sizes, int n_in,
                              void* d_out, int out_size)
{
    const float* query  = (const float*)d_in[0];
    const float* ref    = (const float*)d_in[1];
    const float* value  = (const float*)d_in[2];
    const float* W_off  = (const float*)d_in[3];
    const float* b_off  = (const float*)d_in[4];
    const float* W_attn = (const float*)d_in[5];
    const float* b_attn = (const float*)d_in[6];
    const float* W_val  = (const float*)d_in[7];
    const float* b_val  = (const float*)d_in[8];
    const float* W_out  = (const float*)d_in[9];
    const float* b_out  = (const float*)d_in[10];
    float* out = (float*)d_out;

    float *gv, *goa;
    __nv_bfloat16 *wh, *wl;
    cudaGetSymbolAddress((void**)&gv,  g_v);
    cudaGetSymbolAddress((void**)&goa, g_oa);
    cudaGetSymbolAddress((void**)&wh,  g_wh);
    cudaGetSymbolAddress((void**)&wl,  g_wl);

    cudaFuncSetAttribute(gemm_front, cudaFuncAttributeMaxDynamicSharedMemorySize,
                         SM_TOTAL);
    cudaFuncSetAttribute(gemm_out, cudaFuncAttributeMaxDynamicSharedMemorySize,
                         SM_TOTAL);

    const int MT = LQP / 128;   // 174

    // 0. prep: weight split + A split (value, query)
    prep_all_w<<<(W_TOTAL + 255) / 256, 256>>>(W_val, W_off, W_attn, W_out, wh, wl);
    split_av<<<(2 * LQ * 64 + 255) / 256, 256>>>(value, query);

    // 1. merged front GEMMs: y 0..1 value (N=256), y 2..4 query (N=384)
    gemm_front<<<dim3(MT, 5), 256, SM_TOTAL>>>(wh, wl, b_val, b_off, b_attn,
                                               gv, goa);
    // 2. sampling (softmax fused; 2 queries per block, interleaved gather)
    sample_kernel<<<(LQ + 1) / 2, 256>>>(gv, goa, ref);
    // 3. out = mid @ W_out + b_out
    gemm_out<<<dim3(MT, 2), 256, SM_TOTAL>>>(wh, wl, b_out, out);
}